// round 14
// baseline (speedup 1.0000x reference)
#include <cuda_runtime.h>
#include <cuda_bf16.h>
#include <cstdint>
#include <cstddef>

#define NND 50000
#define NE  500000
#define HD  128
#define NHD 8

// ---------------- scratch (device globals: allocation-free) ----------------
__device__ float g_agg[NND * HD];
__device__ float g_t1 [NND * HD];
__device__ float g_xl [NND * HD];
__device__ float g_q  [NND * HD];
__device__ float g_k  [NND * HD];
__device__ float g_v  [NND * HD];
__device__ float g_xa [NND * HD];
__device__ float g_hc [NND * HD];
__device__ float g_xo [NND * HD];
__device__ float g_ffn[NND * 2 * HD];
__device__ float g_den[NND * NHD];
__device__ float g_sum[3 * HD];
__device__ float g_ssq[3 * HD];

// ---------------- helpers ----------------
__device__ __forceinline__ void red4(float* p, float4 v) {
    asm volatile("red.global.add.v4.f32 [%0], {%1,%2,%3,%4};"
                 :: "l"(p), "f"(v.x), "f"(v.y), "f"(v.z), "f"(v.w) : "memory");
}
__device__ __forceinline__ uint32_t smem_u32(const void* p) {
    uint32_t a;
    asm("{ .reg .u64 t; cvta.to.shared.u64 t, %1; cvt.u32.u64 %0, t; }" : "=r"(a) : "l"(p));
    return a;
}
__device__ __forceinline__ void cp16(uint32_t dst, const float* src, int nbytes) {
    asm volatile("cp.async.ca.shared.global [%0], [%1], 16, %2;"
                 :: "r"(dst), "l"(__cvta_generic_to_global(src)), "r"(nbytes) : "memory");
}
__device__ __forceinline__ uint32_t f2tf32(float f) {
    uint32_t r;
    asm("cvt.rna.tf32.f32 %0, %1;" : "=r"(r) : "f"(f));
    return r;
}
__device__ __forceinline__ void mma_tf32(float* c, const uint32_t* a, const uint32_t* b) {
    asm volatile("mma.sync.aligned.m16n8k8.row.col.f32.tf32.tf32.f32 "
                 "{%0,%1,%2,%3}, {%4,%5,%6,%7}, {%8,%9}, {%0,%1,%2,%3};"
                 : "+f"(c[0]), "+f"(c[1]), "+f"(c[2]), "+f"(c[3])
                 : "r"(a[0]), "r"(a[1]), "r"(a[2]), "r"(a[3]), "r"(b[0]), "r"(b[1]));
}

// ---------------- init scratch (g_agg = h : folds the GINE self-term) ----------------
__global__ void zero_kernel(const float* __restrict__ h) {
    int i = blockIdx.x * blockDim.x + threadIdx.x;
    if (i < NND * HD) { g_agg[i] = h[i]; g_xa[i] = 0.f; }
    if (i < NND * NHD) g_den[i] = 0.f;
    if (i < 3 * HD)   { g_sum[i] = 0.f; g_ssq[i] = 0.f; }
}

// ---------------- GINE message (eattr copy handled by copy engine) ----------------
__global__ void msg_kernel(const float* __restrict__ h, const float* __restrict__ eattr,
                           const int* __restrict__ src, const int* __restrict__ dst) {
    int gid  = blockIdx.x * blockDim.x + threadIdx.x;
    int e    = gid >> 5;
    int lane = gid & 31;
    if (e >= NE) return;
    int sr = src[e], ds = dst[e];
    const float4 hv = *(const float4*)(h + (size_t)sr * HD + lane * 4);
    const float4 ev = *(const float4*)(eattr + (size_t)e * HD + lane * 4);
    float4 m;
    m.x = fmaxf(hv.x + ev.x, 0.f);
    m.y = fmaxf(hv.y + ev.y, 0.f);
    m.z = fmaxf(hv.z + ev.z, 0.f);
    m.w = fmaxf(hv.w + ev.w, 0.f);
    red4(&g_agg[(size_t)ds * HD + lane * 4], m);
}

// ---------------- tf32 mma.sync GEMM, cp.async 2-stage pipeline, fused BN stats ----------------
#define AS_F (64 * 36)
#define WS_F (128 * 36)
#define GEMM_SMEM ((2 * AS_F + 2 * WS_F) * 4)   // 55296 B
__global__ __launch_bounds__(128, 3)
void mma_gemm_kernel(const float* __restrict__ A,
                     const float* __restrict__ W0, const float* __restrict__ W1,
                     const float* __restrict__ W2,
                     const float* __restrict__ b0, const float* __restrict__ b1,
                     const float* __restrict__ b2,
                     const float* __restrict__ addend,
                     float* __restrict__ C0, float* __restrict__ C1, float* __restrict__ C2,
                     int M, int Nn, int Ktot, int doRelu,
                     float s0, float s1, float s2, int statSlot) {
    extern __shared__ float smf[];
    float* Asm[2] = { smf,          smf + AS_F };
    float* Wsm[2] = { smf + 2*AS_F, smf + 2*AS_F + WS_F };
    const uint32_t aB[2] = { smem_u32(Asm[0]), smem_u32(Asm[1]) };
    const uint32_t wB[2] = { smem_u32(Wsm[0]), smem_u32(Wsm[1]) };

    const int nColBlk = Nn >> 7;
    const int sel    = blockIdx.x / nColBlk;
    const int colblk = blockIdx.x - sel * nColBlk;
    const float* W    = (sel == 0) ? W0 : (sel == 1) ? W1 : W2;
    const float* bias = (sel == 0) ? b0 : (sel == 1) ? b1 : b2;
    float* C          = (sel == 0) ? C0 : (sel == 1) ? C1 : C2;
    const float scale = (sel == 0) ? s0 : (sel == 1) ? s1 : s2;

    const int tid  = threadIdx.x;
    const int wid  = tid >> 5;
    const int lane = tid & 31;
    const int gr = lane >> 2;
    const int tg = lane & 3;
    const int wm = wid & 1;
    const int wn = wid >> 1;
    const int row0 = blockIdx.y * 64;
    const int col0 = colblk * 128;

    const int nChunks = Ktot >> 5;

    auto issue = [&](int st, int kc) {
        const int k0 = kc << 5;
#pragma unroll
        for (int it = 0; it < 4; it++) {
            int i = tid + it * 128;
            int r = i >> 3;
            int c = (i & 7) << 2;
            int nb = (row0 + r < M) ? 16 : 0;
            cp16(aB[st] + (uint32_t)(r * 36 + c) * 4,
                 A + (size_t)(row0 + r) * Ktot + k0 + c, nb);
        }
#pragma unroll
        for (int it = 0; it < 8; it++) {
            int i = tid + it * 128;
            int r = i >> 3;
            int c = (i & 7) << 2;
            cp16(wB[st] + (uint32_t)(r * 36 + c) * 4,
                 W + (size_t)(col0 + r) * Ktot + k0 + c, 16);
        }
    };

    float acc[2][8][4];
#pragma unroll
    for (int mt = 0; mt < 2; mt++)
#pragma unroll
        for (int nt = 0; nt < 8; nt++)
#pragma unroll
            for (int j = 0; j < 4; j++) acc[mt][nt][j] = 0.f;

    issue(0, 0);
    asm volatile("cp.async.commit_group;" ::: "memory");

    for (int kc = 0; kc < nChunks; kc++) {
        const int st = kc & 1;
        if (kc + 1 < nChunks) issue(st ^ 1, kc + 1);
        asm volatile("cp.async.commit_group;" ::: "memory");
        asm volatile("cp.async.wait_group 1;" ::: "memory");
        __syncthreads();

        const float* As = Asm[st];
        const float* Ws = Wsm[st];
#pragma unroll
        for (int ks = 0; ks < 4; ks++) {
            const int k0s = ks * 8;
            uint32_t ta[2][4];
#pragma unroll
            for (int mf = 0; mf < 2; mf++) {
                int base = wm * 32 + mf * 16;
                ta[mf][0] = f2tf32(As[(base + gr)     * 36 + k0s + tg]);
                ta[mf][1] = f2tf32(As[(base + gr + 8) * 36 + k0s + tg]);
                ta[mf][2] = f2tf32(As[(base + gr)     * 36 + k0s + tg + 4]);
                ta[mf][3] = f2tf32(As[(base + gr + 8) * 36 + k0s + tg + 4]);
            }
#pragma unroll
            for (int nt = 0; nt < 8; nt++) {
                int n0 = wn * 64 + nt * 8;
                uint32_t tb[2];
                tb[0] = f2tf32(Ws[(n0 + gr) * 36 + k0s + tg]);
                tb[1] = f2tf32(Ws[(n0 + gr) * 36 + k0s + tg + 4]);
                mma_tf32(acc[0][nt], ta[0], tb);
                mma_tf32(acc[1][nt], ta[1], tb);
            }
        }
        __syncthreads();
    }

    const int qc = tg * 2;
#pragma unroll
    for (int nt = 0; nt < 8; nt++) {
        int c = col0 + wn * 64 + nt * 8 + qc;
        float cs0 = 0.f, cs1 = 0.f, cq0 = 0.f, cq1 = 0.f;
#pragma unroll
        for (int mt = 0; mt < 2; mt++) {
#pragma unroll
            for (int half = 0; half < 2; half++) {
                int r = row0 + wm * 32 + mt * 16 + gr + half * 8;
                if (r >= M) continue;
                float v0 = (acc[mt][nt][half * 2 + 0] + bias[c + 0]) * scale;
                float v1 = (acc[mt][nt][half * 2 + 1] + bias[c + 1]) * scale;
                if (doRelu) { v0 = fmaxf(v0, 0.f); v1 = fmaxf(v1, 0.f); }
                if (addend) {
                    float2 ad = *(const float2*)(addend + (size_t)r * Nn + c);
                    v0 += ad.x; v1 += ad.y;
                }
                *(float2*)(C + (size_t)r * Nn + c) = make_float2(v0, v1);
                cs0 += v0; cs1 += v1;
                cq0 += v0 * v0; cq1 += v1 * v1;
            }
        }
        if (statSlot >= 0) {
#pragma unroll
            for (int m = 4; m <= 16; m <<= 1) {
                cs0 += __shfl_xor_sync(0xffffffffu, cs0, m);
                cs1 += __shfl_xor_sync(0xffffffffu, cs1, m);
                cq0 += __shfl_xor_sync(0xffffffffu, cq0, m);
                cq1 += __shfl_xor_sync(0xffffffffu, cq1, m);
            }
            if (gr == 0) {
                int cc = c & (HD - 1);
                atomicAdd(&g_sum[statSlot * HD + cc + 0], cs0);
                atomicAdd(&g_sum[statSlot * HD + cc + 1], cs1);
                atomicAdd(&g_ssq[statSlot * HD + cc + 0], cq0);
                atomicAdd(&g_ssq[statSlot * HD + cc + 1], cq1);
            }
        }
    }
}

// ---------------- fused edge attention: p=exp(q.k); den[src]+=p; xa[src]+=p*v[dst] ----------------
__global__ void attn_edge_kernel(const int* __restrict__ src, const int* __restrict__ dst) {
    int gid  = blockIdx.x * blockDim.x + threadIdx.x;
    int e    = gid >> 5;
    int lane = gid & 31;
    if (e >= NE) return;
    int sr = src[e], ds = dst[e];
    const float4 qv = *(const float4*)(g_q + (size_t)sr * HD + lane * 4);
    const float4 kv = *(const float4*)(g_k + (size_t)ds * HD + lane * 4);
    float part = qv.x * kv.x + qv.y * kv.y + qv.z * kv.z + qv.w * kv.w;
    part += __shfl_xor_sync(0xffffffffu, part, 1);
    part += __shfl_xor_sync(0xffffffffu, part, 2);   // per-head dot (4-lane group)
    float p = __expf(part);
    if ((lane & 3) == 0)
        atomicAdd(&g_den[sr * NHD + (lane >> 2)], p);
    float4 vv = *(const float4*)(g_v + (size_t)ds * HD + lane * 4);
    vv.x *= p; vv.y *= p; vv.z *= p; vv.w *= p;
    red4(&g_xa[(size_t)sr * HD + lane * 4], vv);
}

// ---------------- vectorized xa normalize + residual + BN stats ----------------
__global__ __launch_bounds__(256)
void xa_stats_kernel(const float* __restrict__ h) {
    __shared__ float ssum[HD], sssq[HD];
    int tid  = threadIdx.x;
    int lane = tid & 31;
    int w    = tid >> 5;
    if (tid < HD) { ssum[tid] = 0.f; sssq[tid] = 0.f; }
    __syncthreads();

    int hd = lane >> 2;
    float4 as = make_float4(0.f, 0.f, 0.f, 0.f);
    float4 aq = make_float4(0.f, 0.f, 0.f, 0.f);

    int stride = gridDim.x * 8;
#pragma unroll 4
    for (int r = blockIdx.x * 8 + w; r < NND; r += stride) {
        float4 x  = *(const float4*)(g_xa + (size_t)r * HD + lane * 4);
        float  d  = g_den[r * NHD + hd];
        float4 hr = *(const float4*)(h + (size_t)r * HD + lane * 4);
        float inv = (d > 0.f) ? (1.f / d) : 0.f;
        float4 o;
        o.x = hr.x + x.x * inv;
        o.y = hr.y + x.y * inv;
        o.z = hr.z + x.z * inv;
        o.w = hr.w + x.w * inv;
        *(float4*)(g_xa + (size_t)r * HD + lane * 4) = o;
        as.x += o.x; as.y += o.y; as.z += o.z; as.w += o.w;
        aq.x += o.x * o.x; aq.y += o.y * o.y;
        aq.z += o.z * o.z; aq.w += o.w * o.w;
    }

    int c0 = lane * 4;
    atomicAdd(&ssum[c0 + 0], as.x); atomicAdd(&ssum[c0 + 1], as.y);
    atomicAdd(&ssum[c0 + 2], as.z); atomicAdd(&ssum[c0 + 3], as.w);
    atomicAdd(&sssq[c0 + 0], aq.x); atomicAdd(&sssq[c0 + 1], aq.y);
    atomicAdd(&sssq[c0 + 2], aq.z); atomicAdd(&sssq[c0 + 3], aq.w);
    __syncthreads();
    if (tid < HD) {
        atomicAdd(&g_sum[HD + tid], ssum[tid]);
        atomicAdd(&g_ssq[HD + tid], sssq[tid]);
    }
}

// ---------------- hc = bn0(xl) + bn1(xa) (float4) ----------------
__global__ void combine_kernel(const float* __restrict__ nl_g, const float* __restrict__ nl_b,
                               const float* __restrict__ na_g, const float* __restrict__ na_b) {
    int i = blockIdx.x * blockDim.x + threadIdx.x;
    if (i >= NND * HD / 4) return;
    int c = (i * 4) & (HD - 1);
    const float invN = 1.f / (float)NND;
    float4 xl = *(const float4*)&g_xl[i * 4];
    float4 xa = *(const float4*)&g_xa[i * 4];
    float4 o;
#pragma unroll
    for (int j = 0; j < 4; j++) {
        float mu0 = g_sum[c + j] * invN;
        float v0  = g_ssq[c + j] * invN - mu0 * mu0;
        float i0  = rsqrtf(v0 + 1e-5f);
        float mu1 = g_sum[HD + c + j] * invN;
        float v1  = g_ssq[HD + c + j] * invN - mu1 * mu1;
        float i1  = rsqrtf(v1 + 1e-5f);
        float xlv = (&xl.x)[j], xav = (&xa.x)[j];
        (&o.x)[j] = (xlv - mu0) * i0 * nl_g[c + j] + nl_b[c + j]
                  + (xav - mu1) * i1 * na_g[c + j] + na_b[c + j];
    }
    *(float4*)&g_hc[i * 4] = o;
}

// ---------------- out = bn2(xo) (float4) ----------------
__global__ void apply_kernel(const float* __restrict__ no_g, const float* __restrict__ no_b,
                             float* __restrict__ out) {
    int i = blockIdx.x * blockDim.x + threadIdx.x;
    if (i >= NND * HD / 4) return;
    int c = (i * 4) & (HD - 1);
    const float invN = 1.f / (float)NND;
    float4 x = *(const float4*)&g_xo[i * 4];
    float4 o;
#pragma unroll
    for (int j = 0; j < 4; j++) {
        float mu = g_sum[2 * HD + c + j] * invN;
        float v  = g_ssq[2 * HD + c + j] * invN - mu * mu;
        float iv = rsqrtf(v + 1e-5f);
        (&o.x)[j] = ((&x.x)[j] - mu) * iv * no_g[c + j] + no_b[c + j];
    }
    *(float4*)&out[i * 4] = o;
}

// ---------------- host launcher ----------------
extern "C" void kernel_launch(void* const* d_in, const int* in_sizes, int n_in,
                              void* d_out, int out_size) {
    const float* h      = (const float*)d_in[0];
    const float* eattr  = (const float*)d_in[1];
    const int*   src    = (const int*)  d_in[2];
    const int*   dst    = (const int*)  d_in[3];
    const float* gin_w1 = (const float*)d_in[4];
    const float* gin_b1 = (const float*)d_in[5];
    const float* gin_w2 = (const float*)d_in[6];
    const float* gin_b2 = (const float*)d_in[7];
    const float* wq     = (const float*)d_in[8];
    const float* bq     = (const float*)d_in[9];
    const float* wk     = (const float*)d_in[10];
    const float* bk     = (const float*)d_in[11];
    const float* wv     = (const float*)d_in[12];
    const float* bv     = (const float*)d_in[13];
    const float* nl_g   = (const float*)d_in[14];
    const float* nl_b   = (const float*)d_in[15];
    const float* na_g   = (const float*)d_in[16];
    const float* na_b   = (const float*)d_in[17];
    const float* no_g   = (const float*)d_in[18];
    const float* no_b   = (const float*)d_in[19];
    const float* ffn1_w = (const float*)d_in[20];
    const float* ffn1_b = (const float*)d_in[21];
    const float* ffn2_w = (const float*)d_in[22];
    const float* ffn2_b = (const float*)d_in[23];
    float* out = (float*)d_out;

    float* p_agg; cudaGetSymbolAddress((void**)&p_agg, g_agg);
    float* p_t1;  cudaGetSymbolAddress((void**)&p_t1,  g_t1);
    float* p_xl;  cudaGetSymbolAddress((void**)&p_xl,  g_xl);
    float* p_q;   cudaGetSymbolAddress((void**)&p_q,   g_q);
    float* p_k;   cudaGetSymbolAddress((void**)&p_k,   g_k);
    float* p_v;   cudaGetSymbolAddress((void**)&p_v,   g_v);
    float* p_hc;  cudaGetSymbolAddress((void**)&p_hc,  g_hc);
    float* p_xo;  cudaGetSymbolAddress((void**)&p_xo,  g_xo);
    float* p_ffn; cudaGetSymbolAddress((void**)&p_ffn, g_ffn);

    static cudaStream_t s1 = nullptr, s2 = nullptr;
    static cudaEvent_t evF = nullptr, evJ = nullptr, evC = nullptr;
    if (s1 == nullptr) {
        cudaStreamCreateWithFlags(&s1, cudaStreamNonBlocking);
        cudaStreamCreateWithFlags(&s2, cudaStreamNonBlocking);
        cudaEventCreateWithFlags(&evF, cudaEventDisableTiming);
        cudaEventCreateWithFlags(&evJ, cudaEventDisableTiming);
        cudaEventCreateWithFlags(&evC, cudaEventDisableTiming);
        cudaFuncSetAttribute(mma_gemm_kernel, cudaFuncAttributeMaxDynamicSharedMemorySize, GEMM_SMEM);
    }

    const int M  = NND;
    const int MT = (M + 63) / 64;         // 782
    const float scale = 0.25f;            // DH^-0.5, DH=16

    // ---- common init + fork ----
    zero_kernel<<<(NND * HD + 255) / 256, 256>>>(h);
    cudaEventRecord(evF, 0);

    // ---- stream s2: eattr -> out copy on the copy engine (independent) ----
    cudaStreamWaitEvent(s2, evF, 0);
    cudaMemcpyAsync(out + (size_t)NND * HD, eattr, (size_t)NE * HD * sizeof(float),
                    cudaMemcpyDeviceToDevice, s2);
    cudaEventRecord(evC, s2);

    // ---- chain B (s1): qkv -> edge attention -> xa normalize+stats ----
    cudaStreamWaitEvent(s1, evF, 0);
    mma_gemm_kernel<<<dim3(3, MT), 128, GEMM_SMEM, s1>>>(
        h, wq, wk, wv, bq, bk, bv,
        nullptr, p_q, p_k, p_v, M, HD, HD, 0, scale, 1.f, 1.f, -1);
    attn_edge_kernel<<<(NE * 32 + 255) / 256, 256, 0, s1>>>(src, dst);
    xa_stats_kernel<<<400, 256, 0, s1>>>(h);
    cudaEventRecord(evJ, s1);

    // ---- chain A (capture stream): msg -> gin MLP (stats fused in gin2) ----
    msg_kernel<<<(NE * 32 + 255) / 256, 256>>>(h, eattr, src, dst);
    mma_gemm_kernel<<<dim3(1, MT), 128, GEMM_SMEM>>>(
        p_agg, gin_w1, gin_w1, gin_w1, gin_b1, gin_b1, gin_b1,
        nullptr, p_t1, p_t1, p_t1, M, HD, HD, 1, 1.f, 1.f, 1.f, -1);
    mma_gemm_kernel<<<dim3(1, MT), 128, GEMM_SMEM>>>(
        p_t1, gin_w2, gin_w2, gin_w2, gin_b2, gin_b2, gin_b2,
        h, p_xl, p_xl, p_xl, M, HD, HD, 0, 1.f, 1.f, 1.f, 0);

    // ---- join ----
    cudaStreamWaitEvent(0, evJ, 0);
    combine_kernel<<<(NND * HD / 4 + 255) / 256, 256>>>(nl_g, nl_b, na_g, na_b);

    // ---- FFN + residual (stats fused in ffn2) ----
    mma_gemm_kernel<<<dim3(2, MT), 128, GEMM_SMEM>>>(
        p_hc, ffn1_w, ffn1_w, ffn1_w, ffn1_b, ffn1_b, ffn1_b,
        nullptr, p_ffn, p_ffn, p_ffn, M, 2 * HD, HD, 1, 1.f, 1.f, 1.f, -1);
    mma_gemm_kernel<<<dim3(1, MT), 128, GEMM_SMEM>>>(
        p_ffn, ffn2_w, ffn2_w, ffn2_w, ffn2_b, ffn2_b, ffn2_b,
        p_hc, p_xo, p_xo, p_xo, M, HD, 2 * HD, 0, 1.f, 1.f, 1.f, 2);

    // ---- join copy stream, final BN ----
    cudaStreamWaitEvent(0, evC, 0);
    apply_kernel<<<(NND * HD / 4 + 255) / 256, 256>>>(no_g, no_b, out);
}

// round 15
// speedup vs baseline: 1.1055x; 1.1055x over previous
#include <cuda_runtime.h>
#include <cuda_bf16.h>
#include <cstdint>
#include <cstddef>

#define NND 50000
#define NE  500000
#define HD  128
#define NHD 8

// ---------------- scratch (device globals: allocation-free) ----------------
__device__ float g_agg[NND * HD];
__device__ float g_t1 [NND * HD];
__device__ float g_xl [NND * HD];
__device__ float g_q  [NND * HD];
__device__ float g_k  [NND * HD];
__device__ float g_v  [NND * HD];
__device__ float g_xa [NND * HD];
__device__ float g_hc [NND * HD];
__device__ float g_xo [NND * HD];
__device__ float g_ffn[NND * 2 * HD];
__device__ float g_den[NND * NHD];
__device__ float g_sum[3 * HD];
__device__ float g_ssq[3 * HD];

// ---------------- helpers ----------------
__device__ __forceinline__ void red4(float* p, float4 v) {
    asm volatile("red.global.add.v4.f32 [%0], {%1,%2,%3,%4};"
                 :: "l"(p), "f"(v.x), "f"(v.y), "f"(v.z), "f"(v.w) : "memory");
}
__device__ __forceinline__ uint32_t smem_u32(const void* p) {
    uint32_t a;
    asm("{ .reg .u64 t; cvta.to.shared.u64 t, %1; cvt.u32.u64 %0, t; }" : "=r"(a) : "l"(p));
    return a;
}
__device__ __forceinline__ void cp16(uint32_t dst, const float* src, int nbytes) {
    asm volatile("cp.async.ca.shared.global [%0], [%1], 16, %2;"
                 :: "r"(dst), "l"(__cvta_generic_to_global(src)), "r"(nbytes) : "memory");
}
__device__ __forceinline__ uint32_t f2tf32(float f) {
    uint32_t r;
    asm("cvt.rna.tf32.f32 %0, %1;" : "=r"(r) : "f"(f));
    return r;
}
__device__ __forceinline__ void mma_tf32(float* c, const uint32_t* a, const uint32_t* b) {
    asm volatile("mma.sync.aligned.m16n8k8.row.col.f32.tf32.tf32.f32 "
                 "{%0,%1,%2,%3}, {%4,%5,%6,%7}, {%8,%9}, {%0,%1,%2,%3};"
                 : "+f"(c[0]), "+f"(c[1]), "+f"(c[2]), "+f"(c[3])
                 : "r"(a[0]), "r"(a[1]), "r"(a[2]), "r"(a[3]), "r"(b[0]), "r"(b[1]));
}

// ---------------- init scratch (g_agg = h : folds the GINE self-term) ----------------
__global__ void zero_kernel(const float* __restrict__ h) {
    int i = blockIdx.x * blockDim.x + threadIdx.x;
    if (i < NND * HD) { g_agg[i] = h[i]; g_xa[i] = 0.f; }
    if (i < NND * NHD) g_den[i] = 0.f;
    if (i < 3 * HD)   { g_sum[i] = 0.f; g_ssq[i] = 0.f; }
}

// ---------------- GINE message + eattr passthrough to output ----------------
__global__ void msg_kernel(const float* __restrict__ h, const float* __restrict__ eattr,
                           const int* __restrict__ src, const int* __restrict__ dst,
                           float* __restrict__ out_e) {
    int gid  = blockIdx.x * blockDim.x + threadIdx.x;
    int e    = gid >> 5;
    int lane = gid & 31;
    if (e >= NE) return;
    int sr = src[e], ds = dst[e];
    const float4 hv = *(const float4*)(h + (size_t)sr * HD + lane * 4);
    const float4 ev = *(const float4*)(eattr + (size_t)e * HD + lane * 4);
    *(float4*)(out_e + (size_t)e * HD + lane * 4) = ev;   // fused eattr copy-out
    float4 m;
    m.x = fmaxf(hv.x + ev.x, 0.f);
    m.y = fmaxf(hv.y + ev.y, 0.f);
    m.z = fmaxf(hv.z + ev.z, 0.f);
    m.w = fmaxf(hv.w + ev.w, 0.f);
    red4(&g_agg[(size_t)ds * HD + lane * 4], m);
}

// ---------------- tf32 mma.sync GEMM, cp.async 2-stage pipeline, fused BN stats ----------------
#define AS_F (64 * 36)
#define WS_F (128 * 36)
#define GEMM_SMEM ((2 * AS_F + 2 * WS_F) * 4)   // 55296 B
__global__ __launch_bounds__(128, 3)
void mma_gemm_kernel(const float* __restrict__ A,
                     const float* __restrict__ W0, const float* __restrict__ W1,
                     const float* __restrict__ W2,
                     const float* __restrict__ b0, const float* __restrict__ b1,
                     const float* __restrict__ b2,
                     const float* __restrict__ addend,
                     float* __restrict__ C0, float* __restrict__ C1, float* __restrict__ C2,
                     int M, int Nn, int Ktot, int doRelu,
                     float s0, float s1, float s2, int statSlot) {
    extern __shared__ float smf[];
    float* Asm[2] = { smf,          smf + AS_F };
    float* Wsm[2] = { smf + 2*AS_F, smf + 2*AS_F + WS_F };
    const uint32_t aB[2] = { smem_u32(Asm[0]), smem_u32(Asm[1]) };
    const uint32_t wB[2] = { smem_u32(Wsm[0]), smem_u32(Wsm[1]) };

    const int nColBlk = Nn >> 7;
    const int sel    = blockIdx.x / nColBlk;
    const int colblk = blockIdx.x - sel * nColBlk;
    const float* W    = (sel == 0) ? W0 : (sel == 1) ? W1 : W2;
    const float* bias = (sel == 0) ? b0 : (sel == 1) ? b1 : b2;
    float* C          = (sel == 0) ? C0 : (sel == 1) ? C1 : C2;
    const float scale = (sel == 0) ? s0 : (sel == 1) ? s1 : s2;

    const int tid  = threadIdx.x;
    const int wid  = tid >> 5;
    const int lane = tid & 31;
    const int gr = lane >> 2;
    const int tg = lane & 3;
    const int wm = wid & 1;
    const int wn = wid >> 1;
    const int row0 = blockIdx.y * 64;
    const int col0 = colblk * 128;

    const int nChunks = Ktot >> 5;

    auto issue = [&](int st, int kc) {
        const int k0 = kc << 5;
#pragma unroll
        for (int it = 0; it < 4; it++) {
            int i = tid + it * 128;
            int r = i >> 3;
            int c = (i & 7) << 2;
            int nb = (row0 + r < M) ? 16 : 0;
            cp16(aB[st] + (uint32_t)(r * 36 + c) * 4,
                 A + (size_t)(row0 + r) * Ktot + k0 + c, nb);
        }
#pragma unroll
        for (int it = 0; it < 8; it++) {
            int i = tid + it * 128;
            int r = i >> 3;
            int c = (i & 7) << 2;
            cp16(wB[st] + (uint32_t)(r * 36 + c) * 4,
                 W + (size_t)(col0 + r) * Ktot + k0 + c, 16);
        }
    };

    float acc[2][8][4];
#pragma unroll
    for (int mt = 0; mt < 2; mt++)
#pragma unroll
        for (int nt = 0; nt < 8; nt++)
#pragma unroll
            for (int j = 0; j < 4; j++) acc[mt][nt][j] = 0.f;

    issue(0, 0);
    asm volatile("cp.async.commit_group;" ::: "memory");

    for (int kc = 0; kc < nChunks; kc++) {
        const int st = kc & 1;
        if (kc + 1 < nChunks) issue(st ^ 1, kc + 1);
        asm volatile("cp.async.commit_group;" ::: "memory");
        asm volatile("cp.async.wait_group 1;" ::: "memory");
        __syncthreads();

        const float* As = Asm[st];
        const float* Ws = Wsm[st];
#pragma unroll
        for (int ks = 0; ks < 4; ks++) {
            const int k0s = ks * 8;
            uint32_t ta[2][4];
#pragma unroll
            for (int mf = 0; mf < 2; mf++) {
                int base = wm * 32 + mf * 16;
                ta[mf][0] = f2tf32(As[(base + gr)     * 36 + k0s + tg]);
                ta[mf][1] = f2tf32(As[(base + gr + 8) * 36 + k0s + tg]);
                ta[mf][2] = f2tf32(As[(base + gr)     * 36 + k0s + tg + 4]);
                ta[mf][3] = f2tf32(As[(base + gr + 8) * 36 + k0s + tg + 4]);
            }
#pragma unroll
            for (int nt = 0; nt < 8; nt++) {
                int n0 = wn * 64 + nt * 8;
                uint32_t tb[2];
                tb[0] = f2tf32(Ws[(n0 + gr) * 36 + k0s + tg]);
                tb[1] = f2tf32(Ws[(n0 + gr) * 36 + k0s + tg + 4]);
                mma_tf32(acc[0][nt], ta[0], tb);
                mma_tf32(acc[1][nt], ta[1], tb);
            }
        }
        __syncthreads();
    }

    const int qc = tg * 2;
#pragma unroll
    for (int nt = 0; nt < 8; nt++) {
        int c = col0 + wn * 64 + nt * 8 + qc;
        float cs0 = 0.f, cs1 = 0.f, cq0 = 0.f, cq1 = 0.f;
#pragma unroll
        for (int mt = 0; mt < 2; mt++) {
#pragma unroll
            for (int half = 0; half < 2; half++) {
                int r = row0 + wm * 32 + mt * 16 + gr + half * 8;
                if (r >= M) continue;
                float v0 = (acc[mt][nt][half * 2 + 0] + bias[c + 0]) * scale;
                float v1 = (acc[mt][nt][half * 2 + 1] + bias[c + 1]) * scale;
                if (doRelu) { v0 = fmaxf(v0, 0.f); v1 = fmaxf(v1, 0.f); }
                if (addend) {
                    float2 ad = *(const float2*)(addend + (size_t)r * Nn + c);
                    v0 += ad.x; v1 += ad.y;
                }
                *(float2*)(C + (size_t)r * Nn + c) = make_float2(v0, v1);
                cs0 += v0; cs1 += v1;
                cq0 += v0 * v0; cq1 += v1 * v1;
            }
        }
        if (statSlot >= 0) {
#pragma unroll
            for (int m = 4; m <= 16; m <<= 1) {
                cs0 += __shfl_xor_sync(0xffffffffu, cs0, m);
                cs1 += __shfl_xor_sync(0xffffffffu, cs1, m);
                cq0 += __shfl_xor_sync(0xffffffffu, cq0, m);
                cq1 += __shfl_xor_sync(0xffffffffu, cq1, m);
            }
            if (gr == 0) {
                int cc = c & (HD - 1);
                atomicAdd(&g_sum[statSlot * HD + cc + 0], cs0);
                atomicAdd(&g_sum[statSlot * HD + cc + 1], cs1);
                atomicAdd(&g_ssq[statSlot * HD + cc + 0], cq0);
                atomicAdd(&g_ssq[statSlot * HD + cc + 1], cq1);
            }
        }
    }
}

// ---------------- fused edge attention: p=exp(q.k); den[src]+=p; xa[src]+=p*v[dst] ----------------
__global__ void attn_edge_kernel(const int* __restrict__ src, const int* __restrict__ dst) {
    int gid  = blockIdx.x * blockDim.x + threadIdx.x;
    int e    = gid >> 5;
    int lane = gid & 31;
    if (e >= NE) return;
    int sr = src[e], ds = dst[e];
    const float4 qv = *(const float4*)(g_q + (size_t)sr * HD + lane * 4);
    const float4 kv = *(const float4*)(g_k + (size_t)ds * HD + lane * 4);
    float part = qv.x * kv.x + qv.y * kv.y + qv.z * kv.z + qv.w * kv.w;
    part += __shfl_xor_sync(0xffffffffu, part, 1);
    part += __shfl_xor_sync(0xffffffffu, part, 2);   // per-head dot (4-lane group)
    float p = __expf(part);
    if ((lane & 3) == 0)
        atomicAdd(&g_den[sr * NHD + (lane >> 2)], p);
    float4 vv = *(const float4*)(g_v + (size_t)ds * HD + lane * 4);
    vv.x *= p; vv.y *= p; vv.z *= p; vv.w *= p;
    red4(&g_xa[(size_t)sr * HD + lane * 4], vv);
}

// ---------------- vectorized xa normalize + residual + BN stats ----------------
__global__ __launch_bounds__(256)
void xa_stats_kernel(const float* __restrict__ h) {
    __shared__ float ssum[HD], sssq[HD];
    int tid  = threadIdx.x;
    int lane = tid & 31;
    int w    = tid >> 5;
    if (tid < HD) { ssum[tid] = 0.f; sssq[tid] = 0.f; }
    __syncthreads();

    int hd = lane >> 2;
    float4 as = make_float4(0.f, 0.f, 0.f, 0.f);
    float4 aq = make_float4(0.f, 0.f, 0.f, 0.f);

    int stride = gridDim.x * 8;
#pragma unroll 4
    for (int r = blockIdx.x * 8 + w; r < NND; r += stride) {
        float4 x  = *(const float4*)(g_xa + (size_t)r * HD + lane * 4);
        float  d  = g_den[r * NHD + hd];
        float4 hr = *(const float4*)(h + (size_t)r * HD + lane * 4);
        float inv = (d > 0.f) ? (1.f / d) : 0.f;
        float4 o;
        o.x = hr.x + x.x * inv;
        o.y = hr.y + x.y * inv;
        o.z = hr.z + x.z * inv;
        o.w = hr.w + x.w * inv;
        *(float4*)(g_xa + (size_t)r * HD + lane * 4) = o;
        as.x += o.x; as.y += o.y; as.z += o.z; as.w += o.w;
        aq.x += o.x * o.x; aq.y += o.y * o.y;
        aq.z += o.z * o.z; aq.w += o.w * o.w;
    }

    int c0 = lane * 4;
    atomicAdd(&ssum[c0 + 0], as.x); atomicAdd(&ssum[c0 + 1], as.y);
    atomicAdd(&ssum[c0 + 2], as.z); atomicAdd(&ssum[c0 + 3], as.w);
    atomicAdd(&sssq[c0 + 0], aq.x); atomicAdd(&sssq[c0 + 1], aq.y);
    atomicAdd(&sssq[c0 + 2], aq.z); atomicAdd(&sssq[c0 + 3], aq.w);
    __syncthreads();
    if (tid < HD) {
        atomicAdd(&g_sum[HD + tid], ssum[tid]);
        atomicAdd(&g_ssq[HD + tid], sssq[tid]);
    }
}

// ---------------- hc = bn0(xl) + bn1(xa) ----------------
__global__ void combine_kernel(const float* __restrict__ nl_g, const float* __restrict__ nl_b,
                               const float* __restrict__ na_g, const float* __restrict__ na_b) {
    int i = blockIdx.x * blockDim.x + threadIdx.x;
    if (i >= NND * HD) return;
    int c = i & (HD - 1);
    const float invN = 1.f / (float)NND;
    float mu0 = g_sum[c] * invN;
    float v0  = g_ssq[c] * invN - mu0 * mu0;
    float i0  = rsqrtf(v0 + 1e-5f);
    float mu1 = g_sum[HD + c] * invN;
    float v1  = g_ssq[HD + c] * invN - mu1 * mu1;
    float i1  = rsqrtf(v1 + 1e-5f);
    float a = (g_xl[i] - mu0) * i0 * nl_g[c] + nl_b[c];
    float b = (g_xa[i] - mu1) * i1 * na_g[c] + na_b[c];
    g_hc[i] = a + b;
}

// ---------------- out = bn2(xo) ----------------
__global__ void apply_kernel(const float* __restrict__ no_g, const float* __restrict__ no_b,
                             float* __restrict__ out) {
    int i = blockIdx.x * blockDim.x + threadIdx.x;
    if (i >= NND * HD) return;
    int c = i & (HD - 1);
    const float invN = 1.f / (float)NND;
    float mu = g_sum[2 * HD + c] * invN;
    float v  = g_ssq[2 * HD + c] * invN - mu * mu;
    float iv = rsqrtf(v + 1e-5f);
    out[i] = (g_xo[i] - mu) * iv * no_g[c] + no_b[c];
}

// ---------------- host launcher ----------------
extern "C" void kernel_launch(void* const* d_in, const int* in_sizes, int n_in,
                              void* d_out, int out_size) {
    const float* h      = (const float*)d_in[0];
    const float* eattr  = (const float*)d_in[1];
    const int*   src    = (const int*)  d_in[2];
    const int*   dst    = (const int*)  d_in[3];
    const float* gin_w1 = (const float*)d_in[4];
    const float* gin_b1 = (const float*)d_in[5];
    const float* gin_w2 = (const float*)d_in[6];
    const float* gin_b2 = (const float*)d_in[7];
    const float* wq     = (const float*)d_in[8];
    const float* bq     = (const float*)d_in[9];
    const float* wk     = (const float*)d_in[10];
    const float* bk     = (const float*)d_in[11];
    const float* wv     = (const float*)d_in[12];
    const float* bv     = (const float*)d_in[13];
    const float* nl_g   = (const float*)d_in[14];
    const float* nl_b   = (const float*)d_in[15];
    const float* na_g   = (const float*)d_in[16];
    const float* na_b   = (const float*)d_in[17];
    const float* no_g   = (const float*)d_in[18];
    const float* no_b   = (const float*)d_in[19];
    const float* ffn1_w = (const float*)d_in[20];
    const float* ffn1_b = (const float*)d_in[21];
    const float* ffn2_w = (const float*)d_in[22];
    const float* ffn2_b = (const float*)d_in[23];
    float* out = (float*)d_out;

    float* p_agg; cudaGetSymbolAddress((void**)&p_agg, g_agg);
    float* p_t1;  cudaGetSymbolAddress((void**)&p_t1,  g_t1);
    float* p_xl;  cudaGetSymbolAddress((void**)&p_xl,  g_xl);
    float* p_q;   cudaGetSymbolAddress((void**)&p_q,   g_q);
    float* p_k;   cudaGetSymbolAddress((void**)&p_k,   g_k);
    float* p_v;   cudaGetSymbolAddress((void**)&p_v,   g_v);
    float* p_xa;  cudaGetSymbolAddress((void**)&p_xa,  g_xa);
    float* p_hc;  cudaGetSymbolAddress((void**)&p_hc,  g_hc);
    float* p_xo;  cudaGetSymbolAddress((void**)&p_xo,  g_xo);
    float* p_ffn; cudaGetSymbolAddress((void**)&p_ffn, g_ffn);

    static cudaStream_t s1 = nullptr;
    static cudaEvent_t evF = nullptr, evJ = nullptr;
    if (s1 == nullptr) {
        cudaStreamCreateWithFlags(&s1, cudaStreamNonBlocking);
        cudaEventCreateWithFlags(&evF, cudaEventDisableTiming);
        cudaEventCreateWithFlags(&evJ, cudaEventDisableTiming);
        cudaFuncSetAttribute(mma_gemm_kernel, cudaFuncAttributeMaxDynamicSharedMemorySize, GEMM_SMEM);
    }

    const int M  = NND;
    const int MT = (M + 63) / 64;         // 782
    const float scale = 0.25f;            // DH^-0.5, DH=16

    // ---- common init (xa/den zero needed by chain B) ----
    zero_kernel<<<(NND * HD + 255) / 256, 256>>>(h);
    cudaEventRecord(evF, 0);

    // ---- chain B (stream s1): qkv -> edge attention -> xa normalize+stats ----
    cudaStreamWaitEvent(s1, evF, 0);
    mma_gemm_kernel<<<dim3(3, MT), 128, GEMM_SMEM, s1>>>(
        h, wq, wk, wv, bq, bk, bv,
        nullptr, p_q, p_k, p_v, M, HD, HD, 0, scale, 1.f, 1.f, -1);
    attn_edge_kernel<<<(NE * 32 + 255) / 256, 256, 0, s1>>>(src, dst);
    xa_stats_kernel<<<400, 256, 0, s1>>>(h);
    cudaEventRecord(evJ, s1);

    // ---- chain A (capture stream): msg -> gin MLP (stats fused in gin2) ----
    msg_kernel<<<(NE * 32 + 255) / 256, 256>>>(h, eattr, src, dst, out + (size_t)NND * HD);
    mma_gemm_kernel<<<dim3(1, MT), 128, GEMM_SMEM>>>(
        p_agg, gin_w1, gin_w1, gin_w1, gin_b1, gin_b1, gin_b1,
        nullptr, p_t1, p_t1, p_t1, M, HD, HD, 1, 1.f, 1.f, 1.f, -1);
    mma_gemm_kernel<<<dim3(1, MT), 128, GEMM_SMEM>>>(
        p_t1, gin_w2, gin_w2, gin_w2, gin_b2, gin_b2, gin_b2,
        h, p_xl, p_xl, p_xl, M, HD, HD, 0, 1.f, 1.f, 1.f, 0);

    // ---- join ----
    cudaStreamWaitEvent(0, evJ, 0);
    combine_kernel<<<(NND * HD + 255) / 256, 256>>>(nl_g, nl_b, na_g, na_b);

    // ---- FFN + residual (stats fused in ffn2) ----
    mma_gemm_kernel<<<dim3(2, MT), 128, GEMM_SMEM>>>(
        p_hc, ffn1_w, ffn1_w, ffn1_w, ffn1_b, ffn1_b, ffn1_b,
        nullptr, p_ffn, p_ffn, p_ffn, M, 2 * HD, HD, 1, 1.f, 1.f, 1.f, -1);
    mma_gemm_kernel<<<dim3(1, MT), 128, GEMM_SMEM>>>(
        p_ffn, ffn2_w, ffn2_w, ffn2_w, ffn2_b, ffn2_b, ffn2_b,
        p_hc, p_xo, p_xo, p_xo, M, HD, 2 * HD, 0, 1.f, 1.f, 1.f, 2);

    apply_kernel<<<(NND * HD + 255) / 256, 256>>>(no_g, no_b, out);
}